// round 3
// baseline (speedup 1.0000x reference)
#include <cuda_runtime.h>

#define NG   4096
#define HH   128
#define WW   128
#define NPIX (HH*WW)
#define EPSF 1e-6f
#define LOG2E 1.4426950408889634f
#define SXY  31.75f   // (128-1)/2 * 0.5
#define OFFC 63.5f
#define GPB  512      // gaussians per chunk
#define NCHUNK (NG/GPB)

__device__ float4 g_p0[NG];
__device__ float4 g_p1[NG];

__global__ void prep_kernel(const float* __restrict__ means,
                            const float* __restrict__ raw_scales,
                            const float* __restrict__ rotors,
                            const float* __restrict__ t_ptr,
                            const float* __restrict__ angle_ptr,
                            float* __restrict__ out)
{
    int n = blockIdx.x * blockDim.x + threadIdx.x;
    if (n >= NG) return;

    // zero the output image (16384 floats = 4096 float4)
    ((float4*)out)[n] = make_float4(0.f, 0.f, 0.f, 0.f);

    float t     = *t_ptr;
    float angle = *angle_ptr;

    float r[8];
#pragma unroll
    for (int i = 0; i < 8; i++) r[i] = rotors[8*n + i];

    // q1 = normalize(rotors[:, [0,4,5,6]])
    float q1w = r[0], q1x = r[4], q1y = r[5], q1z = r[6];
    {
        float nn = sqrtf(q1w*q1w + q1x*q1x + q1y*q1y + q1z*q1z);
        float inv = 1.f / fmaxf(nn, 1e-12f);
        q1w *= inv; q1x *= inv; q1y *= inv; q1z *= inv;
    }
    // q2 = normalize(rotors[:, [7,1,2,3]] * [1,-1,-1,-1])
    float q2w = r[7], q2x = -r[1], q2y = -r[2], q2z = -r[3];
    {
        float nn = sqrtf(q2w*q2w + q2x*q2x + q2y*q2y + q2z*q2z);
        float inv = 1.f / fmaxf(nn, 1e-12f);
        q2w *= inv; q2x *= inv; q2y *= inv; q2z *= inv;
    }

    float L[4][4]  = {{q1w,-q1x,-q1y,-q1z},
                      {q1x, q1w,-q1z, q1y},
                      {q1y, q1z, q1w,-q1x},
                      {q1z,-q1y, q1x, q1w}};
    float Rm[4][4] = {{ q2w, q2x, q2y, q2z},
                      {-q2x, q2w, q2z,-q2y},
                      {-q2y,-q2z, q2w, q2x},
                      {-q2z, q2y,-q2x, q2w}};
    float R4[4][4];
#pragma unroll
    for (int i = 0; i < 4; i++)
#pragma unroll
        for (int k = 0; k < 4; k++)
            R4[i][k] = L[i][0]*Rm[0][k] + L[i][1]*Rm[1][k]
                     + L[i][2]*Rm[2][k] + L[i][3]*Rm[3][k];

    float s2[4];
#pragma unroll
    for (int j = 0; j < 4; j++) s2[j] = expf(2.f * raw_scales[4*n + j]);

    // cov4D[i][k] = sum_j R4[i][j]*s2[j]*R4[k][j]  (upper triangle)
    float cov[4][4];
#pragma unroll
    for (int i = 0; i < 4; i++)
#pragma unroll
        for (int k = i; k < 4; k++)
            cov[i][k] = R4[i][0]*s2[0]*R4[k][0] + R4[i][1]*s2[1]*R4[k][1]
                      + R4[i][2]*s2[2]*R4[k][2] + R4[i][3]*s2[3]*R4[k][3];

    float Wm   = fmaxf(cov[3][3], EPSF);
    float invW = 1.f / Wm;
    float td   = t - means[4*n + 3];

    float mx = means[4*n+0] + cov[0][3] * td * invW;
    float my = means[4*n+1] + cov[1][3] * td * invW;
    float mz = means[4*n+2] + cov[2][3] * td * invW;

    float ca = cosf(angle), sa = sinf(angle);
    float mvx = ca*mx + sa*mz;
    float mvy = my;

    // cov3D = U - V V^T / Wm
    float M00 = cov[0][0] - cov[0][3]*cov[0][3]*invW;
    float M01 = cov[0][1] - cov[0][3]*cov[1][3]*invW;
    float M02 = cov[0][2] - cov[0][3]*cov[2][3]*invW;
    float M11 = cov[1][1] - cov[1][3]*cov[1][3]*invW;
    float M12 = cov[1][2] - cov[1][3]*cov[2][3]*invW;
    float M22 = cov[2][2] - cov[2][3]*cov[2][3]*invW;

    // view rotation about y, then 2D scale
    float c00 = ca*ca*M00 + 2.f*ca*sa*M02 + sa*sa*M22;
    float c01 = ca*M01 + sa*M12;
    float c11 = M11;

    float a = SXY*SXY*c00 + EPSF;
    float b = SXY*SXY*c01;
    float d = SXY*SXY*c11 + EPSF;
    float det = a*d - b*b;
    float invdet = 1.f / det;

    float mux = SXY*mvx + OFFC;
    float muy = SXY*mvy + OFFC;

    // expo = -0.5*(ia*dx^2 + 2*ib*dx*dy + id*dy^2), ia=d/det, ib=-b/det, id=a/det
    // folded into exp2 domain with log2(weight)
    float ia2 = -0.5f * LOG2E * d * invdet;
    float ib2 =         LOG2E * b * invdet;
    float id2 = -0.5f * LOG2E * a * invdet;
    float lw  = -0.5f * td * td * invW * LOG2E;

    g_p0[n] = make_float4(mux, muy, ia2, ib2);
    g_p1[n] = make_float4(id2, lw, 0.f, 0.f);
}

__global__ void __launch_bounds__(256) render_kernel(float* __restrict__ out)
{
    __shared__ float4 s0[GPB];
    __shared__ float4 s1[GPB];

    int gbase = blockIdx.y * GPB;
    for (int i = threadIdx.x; i < GPB; i += 256) {
        s0[i] = g_p0[gbase + i];
        s1[i] = g_p1[gbase + i];
    }
    __syncthreads();

    int pix = blockIdx.x * 256 + threadIdx.x;
    float x = (float)(pix & (WW - 1));
    float y = (float)(pix >> 7);

    float sum = 0.f;
#pragma unroll 8
    for (int g = 0; g < GPB; g++) {
        float4 p0 = s0[g];
        float4 p1 = s1[g];
        float dx = x - p0.x;
        float dy = y - p0.y;
        float e = fmaf(p0.z * dx, dx, p1.y);   // ia2*dx^2 + lw
        e = fmaf(p0.w * dx, dy, e);            // + ib2*dx*dy
        e = fmaf(p1.x * dy, dy, e);            // + id2*dy^2
        sum += exp2f(e);
    }
    atomicAdd(&out[pix], sum);
}

__global__ void __launch_bounds__(1024) normalize_kernel(float* __restrict__ out)
{
    __shared__ float smax[32];
    float m = 0.f;
    for (int i = threadIdx.x; i < NPIX; i += 1024)
        m = fmaxf(m, out[i]);
#pragma unroll
    for (int o = 16; o; o >>= 1)
        m = fmaxf(m, __shfl_xor_sync(0xFFFFFFFFu, m, o));
    if ((threadIdx.x & 31) == 0) smax[threadIdx.x >> 5] = m;
    __syncthreads();
    if (threadIdx.x < 32) {
        m = smax[threadIdx.x];
#pragma unroll
        for (int o = 16; o; o >>= 1)
            m = fmaxf(m, __shfl_xor_sync(0xFFFFFFFFu, m, o));
        if (threadIdx.x == 0) smax[0] = fmaxf(m, EPSF);
    }
    __syncthreads();
    float inv = 1.f / smax[0];
    for (int i = threadIdx.x; i < NPIX; i += 1024)
        out[i] *= inv;
}

extern "C" void kernel_launch(void* const* d_in, const int* in_sizes, int n_in,
                              void* d_out, int out_size)
{
    const float* means      = (const float*)d_in[0];
    const float* raw_scales = (const float*)d_in[1];
    const float* rotors     = (const float*)d_in[2];
    const float* t_ptr      = (const float*)d_in[3];
    const float* angle_ptr  = (const float*)d_in[4];
    float* out = (float*)d_out;

    prep_kernel<<<NG/256, 256>>>(means, raw_scales, rotors, t_ptr, angle_ptr, out);
    render_kernel<<<dim3(NPIX/256, NCHUNK), 256>>>(out);
    normalize_kernel<<<1, 1024>>>(out);
}

// round 4
// speedup vs baseline: 1.4692x; 1.4692x over previous
#include <cuda_runtime.h>

#define NG   4096
#define HH   128
#define WW   128
#define NPIX (HH*WW)
#define EPSF 1e-6f
#define LOG2E 1.4426950408889634f
#define SXY  31.75f   // (128-1)/2 * 0.5
#define OFFC 63.5f
#define GPB  512      // gaussians per chunk
#define NCHUNK (NG/GPB)

// Pair-interleaved expanded-quadratic coefficients:
// pair p holds [A0,A1, B0,B1, C0,C1, D0,D1, E0,E1, F0,F1] (12 floats = 48B)
__device__ float g_coef[NG * 6];

typedef unsigned long long u64;

__device__ __forceinline__ u64 pack2(float a, float b) {
    u64 r; asm("mov.b64 %0, {%1, %2};" : "=l"(r) : "f"(a), "f"(b)); return r;
}
__device__ __forceinline__ u64 fma2(u64 a, u64 b, u64 c) {
    u64 d; asm("fma.rn.f32x2 %0, %1, %2, %3;" : "=l"(d) : "l"(a), "l"(b), "l"(c)); return d;
}
__device__ __forceinline__ void unpack2(float& lo, float& hi, u64 v) {
    asm("mov.b64 {%0, %1}, %2;" : "=f"(lo), "=f"(hi) : "l"(v));
}
__device__ __forceinline__ float ex2(float x) {
    float r; asm("ex2.approx.ftz.f32 %0, %1;" : "=f"(r) : "f"(x)); return r;
}

__global__ void prep_kernel(const float* __restrict__ means,
                            const float* __restrict__ raw_scales,
                            const float* __restrict__ rotors,
                            const float* __restrict__ t_ptr,
                            const float* __restrict__ angle_ptr,
                            float* __restrict__ out)
{
    int n = blockIdx.x * blockDim.x + threadIdx.x;
    if (n >= NG) return;

    // zero the output image (16384 floats = 4096 float4)
    ((float4*)out)[n] = make_float4(0.f, 0.f, 0.f, 0.f);

    float t     = *t_ptr;
    float angle = *angle_ptr;

    float r[8];
#pragma unroll
    for (int i = 0; i < 8; i++) r[i] = rotors[8*n + i];

    // q1 = normalize(rotors[:, [0,4,5,6]])
    float q1w = r[0], q1x = r[4], q1y = r[5], q1z = r[6];
    {
        float n2 = q1w*q1w + q1x*q1x + q1y*q1y + q1z*q1z;
        float inv = rsqrtf(fmaxf(n2, 1e-24f));
        q1w *= inv; q1x *= inv; q1y *= inv; q1z *= inv;
    }
    // q2 = normalize(rotors[:, [7,1,2,3]] * [1,-1,-1,-1])
    float q2w = r[7], q2x = -r[1], q2y = -r[2], q2z = -r[3];
    {
        float n2 = q2w*q2w + q2x*q2x + q2y*q2y + q2z*q2z;
        float inv = rsqrtf(fmaxf(n2, 1e-24f));
        q2w *= inv; q2x *= inv; q2y *= inv; q2z *= inv;
    }

    float L[4][4]  = {{q1w,-q1x,-q1y,-q1z},
                      {q1x, q1w,-q1z, q1y},
                      {q1y, q1z, q1w,-q1x},
                      {q1z,-q1y, q1x, q1w}};
    float Rm[4][4] = {{ q2w, q2x, q2y, q2z},
                      {-q2x, q2w, q2z,-q2y},
                      {-q2y,-q2z, q2w, q2x},
                      {-q2z, q2y,-q2x, q2w}};
    float R4[4][4];
#pragma unroll
    for (int i = 0; i < 4; i++)
#pragma unroll
        for (int k = 0; k < 4; k++)
            R4[i][k] = L[i][0]*Rm[0][k] + L[i][1]*Rm[1][k]
                     + L[i][2]*Rm[2][k] + L[i][3]*Rm[3][k];

    float s2[4];
#pragma unroll
    for (int j = 0; j < 4; j++) s2[j] = __expf(2.f * raw_scales[4*n + j]);

    // cov4D[i][k] = sum_j R4[i][j]*s2[j]*R4[k][j]  (upper triangle)
    float cov[4][4];
#pragma unroll
    for (int i = 0; i < 4; i++)
#pragma unroll
        for (int k = i; k < 4; k++)
            cov[i][k] = R4[i][0]*s2[0]*R4[k][0] + R4[i][1]*s2[1]*R4[k][1]
                      + R4[i][2]*s2[2]*R4[k][2] + R4[i][3]*s2[3]*R4[k][3];

    float Wm   = fmaxf(cov[3][3], EPSF);
    float invW = __fdividef(1.f, Wm);
    float td   = t - means[4*n + 3];

    float mx = means[4*n+0] + cov[0][3] * td * invW;
    float my = means[4*n+1] + cov[1][3] * td * invW;
    float mz = means[4*n+2] + cov[2][3] * td * invW;

    float ca = __cosf(angle), sa = __sinf(angle);
    float mvx = ca*mx + sa*mz;
    float mvy = my;

    // cov3D = U - V V^T / Wm
    float M00 = cov[0][0] - cov[0][3]*cov[0][3]*invW;
    float M01 = cov[0][1] - cov[0][3]*cov[1][3]*invW;
    float M02 = cov[0][2] - cov[0][3]*cov[2][3]*invW;
    float M11 = cov[1][1] - cov[1][3]*cov[1][3]*invW;
    float M12 = cov[1][2] - cov[1][3]*cov[2][3]*invW;
    float M22 = cov[2][2] - cov[2][3]*cov[2][3]*invW;

    // view rotation about y, then 2D scale
    float c00 = ca*ca*M00 + 2.f*ca*sa*M02 + sa*sa*M22;
    float c01 = ca*M01 + sa*M12;
    float c11 = M11;

    float a = SXY*SXY*c00 + EPSF;
    float b = SXY*SXY*c01;
    float d = SXY*SXY*c11 + EPSF;
    float det = a*d - b*b;
    float invdet = __fdividef(1.f, det);

    float mux = SXY*mvx + OFFC;
    float muy = SXY*mvy + OFFC;

    // quadratic in dx,dy (exp2 domain, weight folded in):
    float A  = -0.5f * LOG2E * d * invdet;   // * dx^2
    float B  =         LOG2E * b * invdet;   // * dx*dy
    float C  = -0.5f * LOG2E * a * invdet;   // * dy^2
    float lw = -0.5f * td * td * invW * LOG2E;

    // expand: e = A x^2 + B xy + C y^2 + D x + E y + F
    float D_ = -2.f*A*mux - B*muy;
    float E_ = -2.f*C*muy - B*mux;
    float F_ = A*mux*mux + B*mux*muy + C*muy*muy + lw;

    int p = n >> 1, l = n & 1;
    float* dst = g_coef + 12*p + l;
    dst[0]  = A;
    dst[2]  = B;
    dst[4]  = C;
    dst[6]  = D_;
    dst[8]  = E_;
    dst[10] = F_;
}

__global__ void __launch_bounds__(256) render_kernel(float* __restrict__ out)
{
    // GPB/2 pairs * 12 floats = 3072 floats = 12 KB
    __shared__ float sc[GPB/2 * 12];

    // stage coefficients: 768 float4 per chunk
    {
        const float4* src = ((const float4*)g_coef) + blockIdx.y * (GPB/2 * 3);
        float4* dst = (float4*)sc;
        for (int i = threadIdx.x; i < GPB/2 * 3; i += 256)
            dst[i] = src[i];
    }
    __syncthreads();

    int pix = blockIdx.x * 256 + threadIdx.x;
    float x = (float)(pix & (WW - 1));
    float y = (float)(pix >> 7);

    u64 X2 = pack2(x*x, x*x);
    u64 XY = pack2(x*y, x*y);
    u64 Y2 = pack2(y*y, y*y);
    u64 Xp = pack2(x, x);
    u64 Yp = pack2(y, y);

    float sum0 = 0.f, sum1 = 0.f;
    const ulonglong2* cp = (const ulonglong2*)sc;
#pragma unroll 8
    for (int g = 0; g < GPB/2; g++) {
        ulonglong2 u0 = cp[3*g + 0];   // {A0A1, B0B1}
        ulonglong2 u1 = cp[3*g + 1];   // {C0C1, D0D1}
        ulonglong2 u2 = cp[3*g + 2];   // {E0E1, F0F1}
        u64 e = u2.y;                  // F
        e = fma2(u0.x, X2, e);
        e = fma2(u0.y, XY, e);
        e = fma2(u1.x, Y2, e);
        e = fma2(u1.y, Xp, e);
        e = fma2(u2.x, Yp, e);
        float e0, e1;
        unpack2(e0, e1, e);
        sum0 += ex2(e0);
        sum1 += ex2(e1);
    }
    atomicAdd(&out[pix], sum0 + sum1);
}

__global__ void __launch_bounds__(1024) normalize_kernel(float* __restrict__ out)
{
    __shared__ float smax[32];
    float4* o4 = (float4*)out;
    float m = 0.f;
#pragma unroll
    for (int i = threadIdx.x; i < NPIX/4; i += 1024) {
        float4 v = o4[i];
        m = fmaxf(m, fmaxf(fmaxf(v.x, v.y), fmaxf(v.z, v.w)));
    }
#pragma unroll
    for (int o = 16; o; o >>= 1)
        m = fmaxf(m, __shfl_xor_sync(0xFFFFFFFFu, m, o));
    if ((threadIdx.x & 31) == 0) smax[threadIdx.x >> 5] = m;
    __syncthreads();
    if (threadIdx.x < 32) {
        m = smax[threadIdx.x];
#pragma unroll
        for (int o = 16; o; o >>= 1)
            m = fmaxf(m, __shfl_xor_sync(0xFFFFFFFFu, m, o));
        if (threadIdx.x == 0) smax[0] = fmaxf(m, EPSF);
    }
    __syncthreads();
    float inv = __fdividef(1.f, smax[0]);
#pragma unroll
    for (int i = threadIdx.x; i < NPIX/4; i += 1024) {
        float4 v = o4[i];
        v.x *= inv; v.y *= inv; v.z *= inv; v.w *= inv;
        o4[i] = v;
    }
}

extern "C" void kernel_launch(void* const* d_in, const int* in_sizes, int n_in,
                              void* d_out, int out_size)
{
    const float* means      = (const float*)d_in[0];
    const float* raw_scales = (const float*)d_in[1];
    const float* rotors     = (const float*)d_in[2];
    const float* t_ptr      = (const float*)d_in[3];
    const float* angle_ptr  = (const float*)d_in[4];
    float* out = (float*)d_out;

    prep_kernel<<<NG/256, 256>>>(means, raw_scales, rotors, t_ptr, angle_ptr, out);
    render_kernel<<<dim3(NPIX/256, NCHUNK), 256>>>(out);
    normalize_kernel<<<1, 1024>>>(out);
}

// round 5
// speedup vs baseline: 2.2008x; 1.4980x over previous
#include <cuda_runtime.h>

#define NG   4096
#define HH   128
#define WW   128
#define NPIX (HH*WW)
#define EPSF 1e-6f
#define LOG2E 1.4426950408889634f
#define SXY  31.75f   // (128-1)/2 * 0.5
#define OFFC 63.5f
#define GPB  128      // gaussians per chunk
#define NCHUNK (NG/GPB)

// Pair-interleaved expanded-quadratic coefficients:
// pair p holds [A0,A1, B0,B1, C0,C1, D0,D1, E0,E1, F0,F1] (12 floats = 48B)
__device__ float g_coef[NG * 6];

typedef unsigned long long u64;

__device__ __forceinline__ u64 pack2(float a, float b) {
    u64 r; asm("mov.b64 %0, {%1, %2};" : "=l"(r) : "f"(a), "f"(b)); return r;
}
__device__ __forceinline__ u64 fma2(u64 a, u64 b, u64 c) {
    u64 d; asm("fma.rn.f32x2 %0, %1, %2, %3;" : "=l"(d) : "l"(a), "l"(b), "l"(c)); return d;
}
__device__ __forceinline__ u64 add2(u64 a, u64 b) {
    u64 d; asm("add.rn.f32x2 %0, %1, %2;" : "=l"(d) : "l"(a), "l"(b)); return d;
}
__device__ __forceinline__ void unpack2(float& lo, float& hi, u64 v) {
    asm("mov.b64 {%0, %1}, %2;" : "=f"(lo), "=f"(hi) : "l"(v));
}
__device__ __forceinline__ float ex2(float x) {
    float r; asm("ex2.approx.ftz.f32 %0, %1;" : "=f"(r) : "f"(x)); return r;
}
// exp both halves of a packed value, repacked (pack/unpack are reg-pair movs)
__device__ __forceinline__ u64 ex2_2(u64 v) {
    float lo, hi; unpack2(lo, hi, v);
    return pack2(ex2(lo), ex2(hi));
}

__global__ void prep_kernel(const float* __restrict__ means,
                            const float* __restrict__ raw_scales,
                            const float* __restrict__ rotors,
                            const float* __restrict__ t_ptr,
                            const float* __restrict__ angle_ptr,
                            float* __restrict__ out)
{
    int n = blockIdx.x * blockDim.x + threadIdx.x;
    if (n >= NG) return;

    // zero the output image (16384 floats = 4096 float4)
    ((float4*)out)[n] = make_float4(0.f, 0.f, 0.f, 0.f);

    float t     = *t_ptr;
    float angle = *angle_ptr;

    float r[8];
#pragma unroll
    for (int i = 0; i < 8; i++) r[i] = rotors[8*n + i];

    // q1 = normalize(rotors[:, [0,4,5,6]])
    float q1w = r[0], q1x = r[4], q1y = r[5], q1z = r[6];
    {
        float n2 = q1w*q1w + q1x*q1x + q1y*q1y + q1z*q1z;
        float inv = rsqrtf(fmaxf(n2, 1e-24f));
        q1w *= inv; q1x *= inv; q1y *= inv; q1z *= inv;
    }
    // q2 = normalize(rotors[:, [7,1,2,3]] * [1,-1,-1,-1])
    float q2w = r[7], q2x = -r[1], q2y = -r[2], q2z = -r[3];
    {
        float n2 = q2w*q2w + q2x*q2x + q2y*q2y + q2z*q2z;
        float inv = rsqrtf(fmaxf(n2, 1e-24f));
        q2w *= inv; q2x *= inv; q2y *= inv; q2z *= inv;
    }

    float L[4][4]  = {{q1w,-q1x,-q1y,-q1z},
                      {q1x, q1w,-q1z, q1y},
                      {q1y, q1z, q1w,-q1x},
                      {q1z,-q1y, q1x, q1w}};
    float Rm[4][4] = {{ q2w, q2x, q2y, q2z},
                      {-q2x, q2w, q2z,-q2y},
                      {-q2y,-q2z, q2w, q2x},
                      {-q2z, q2y,-q2x, q2w}};
    float R4[4][4];
#pragma unroll
    for (int i = 0; i < 4; i++)
#pragma unroll
        for (int k = 0; k < 4; k++)
            R4[i][k] = L[i][0]*Rm[0][k] + L[i][1]*Rm[1][k]
                     + L[i][2]*Rm[2][k] + L[i][3]*Rm[3][k];

    float s2[4];
#pragma unroll
    for (int j = 0; j < 4; j++) s2[j] = __expf(2.f * raw_scales[4*n + j]);

    // cov4D[i][k] = sum_j R4[i][j]*s2[j]*R4[k][j]  (upper triangle)
    float cov[4][4];
#pragma unroll
    for (int i = 0; i < 4; i++)
#pragma unroll
        for (int k = i; k < 4; k++)
            cov[i][k] = R4[i][0]*s2[0]*R4[k][0] + R4[i][1]*s2[1]*R4[k][1]
                      + R4[i][2]*s2[2]*R4[k][2] + R4[i][3]*s2[3]*R4[k][3];

    float Wm   = fmaxf(cov[3][3], EPSF);
    float invW = __fdividef(1.f, Wm);
    float td   = t - means[4*n + 3];

    float mx = means[4*n+0] + cov[0][3] * td * invW;
    float my = means[4*n+1] + cov[1][3] * td * invW;
    float mz = means[4*n+2] + cov[2][3] * td * invW;

    float ca = __cosf(angle), sa = __sinf(angle);
    float mvx = ca*mx + sa*mz;
    float mvy = my;

    // cov3D = U - V V^T / Wm
    float M00 = cov[0][0] - cov[0][3]*cov[0][3]*invW;
    float M01 = cov[0][1] - cov[0][3]*cov[1][3]*invW;
    float M02 = cov[0][2] - cov[0][3]*cov[2][3]*invW;
    float M11 = cov[1][1] - cov[1][3]*cov[1][3]*invW;
    float M12 = cov[1][2] - cov[1][3]*cov[2][3]*invW;
    float M22 = cov[2][2] - cov[2][3]*cov[2][3]*invW;

    // view rotation about y, then 2D scale
    float c00 = ca*ca*M00 + 2.f*ca*sa*M02 + sa*sa*M22;
    float c01 = ca*M01 + sa*M12;
    float c11 = M11;

    float a = SXY*SXY*c00 + EPSF;
    float b = SXY*SXY*c01;
    float d = SXY*SXY*c11 + EPSF;
    float det = a*d - b*b;
    float invdet = __fdividef(1.f, det);

    float mux = SXY*mvx + OFFC;
    float muy = SXY*mvy + OFFC;

    // quadratic in dx,dy (exp2 domain, weight folded in):
    float A  = -0.5f * LOG2E * d * invdet;   // * dx^2
    float B  =         LOG2E * b * invdet;   // * dx*dy
    float C  = -0.5f * LOG2E * a * invdet;   // * dy^2
    float lw = -0.5f * td * td * invW * LOG2E;

    // expand: e = A x^2 + B xy + C y^2 + D x + E y + F
    float D_ = -2.f*A*mux - B*muy;
    float E_ = -2.f*C*muy - B*mux;
    float F_ = A*mux*mux + B*mux*muy + C*muy*muy + lw;

    int p = n >> 1, l = n & 1;
    float* dst = g_coef + 12*p + l;
    dst[0]  = A;
    dst[2]  = B;
    dst[4]  = C;
    dst[6]  = D_;
    dst[8]  = E_;
    dst[10] = F_;
}

// 256 threads, each owns 4 pixels in a column (same x, rows y..y+3).
// Block covers 1024 pixels = 8 rows. grid = (NPIX/1024, NCHUNK).
__global__ void __launch_bounds__(256) render_kernel(float* __restrict__ out)
{
    // GPB/2 pairs * 12 floats = 768 floats = 3 KB = 192 float4
    __shared__ float sc[GPB/2 * 12];

    {
        const float4* src = ((const float4*)g_coef) + blockIdx.y * (GPB/2 * 3);
        if (threadIdx.x < GPB/2 * 3)
            ((float4*)sc)[threadIdx.x] = src[threadIdx.x];
    }
    __syncthreads();

    int x  = threadIdx.x & (WW - 1);
    int y0 = blockIdx.x * 8 + ((threadIdx.x >> 7) << 2);
    float xf = (float)x;
    float yf = (float)y0;

    u64 X2   = pack2(xf*xf, xf*xf);
    u64 XY   = pack2(xf*yf, xf*yf);
    u64 Y2   = pack2(yf*yf, yf*yf);
    u64 Xp   = pack2(xf, xf);
    u64 Yp   = pack2(yf, yf);
    u64 Y2p1 = pack2(2.f*yf + 1.f, 2.f*yf + 1.f);

    u64 s0 = 0, s1 = 0, s2 = 0, s3 = 0;  // packed zero == {0.f,0.f}
    const ulonglong2* cp = (const ulonglong2*)sc;
#pragma unroll 4
    for (int g = 0; g < GPB/2; g++) {
        ulonglong2 u0 = cp[3*g + 0];   // {A, B}
        ulonglong2 u1 = cp[3*g + 1];   // {C, D}
        ulonglong2 u2 = cp[3*g + 2];   // {E, F}

        // e0 at (x, y0)
        u64 e0 = u2.y;
        e0 = fma2(u0.x, X2, e0);
        e0 = fma2(u0.y, XY, e0);
        e0 = fma2(u1.x, Y2, e0);
        e0 = fma2(u1.y, Xp, e0);
        e0 = fma2(u2.x, Yp, e0);

        // forward differences along y: d1 = B*x + C*(2y+1) + E, d2 = 2C
        u64 G  = fma2(u0.y, Xp, fma2(u1.x, Y2p1, u2.x));
        u64 C2 = add2(u1.x, u1.x);
        u64 e1 = add2(e0, G);
        u64 H  = add2(G, C2);
        u64 e2 = add2(e1, H);
        u64 H2 = add2(H, C2);
        u64 e3 = add2(e2, H2);

        s0 = add2(s0, ex2_2(e0));
        s1 = add2(s1, ex2_2(e1));
        s2 = add2(s2, ex2_2(e2));
        s3 = add2(s3, ex2_2(e3));
    }

    float lo, hi;
    unpack2(lo, hi, s0); atomicAdd(&out[(y0+0)*WW + x], lo + hi);
    unpack2(lo, hi, s1); atomicAdd(&out[(y0+1)*WW + x], lo + hi);
    unpack2(lo, hi, s2); atomicAdd(&out[(y0+2)*WW + x], lo + hi);
    unpack2(lo, hi, s3); atomicAdd(&out[(y0+3)*WW + x], lo + hi);
}

__global__ void __launch_bounds__(1024) normalize_kernel(float* __restrict__ out)
{
    __shared__ float smax[32];
    float4* o4 = (float4*)out;
    float m = 0.f;
#pragma unroll
    for (int i = threadIdx.x; i < NPIX/4; i += 1024) {
        float4 v = o4[i];
        m = fmaxf(m, fmaxf(fmaxf(v.x, v.y), fmaxf(v.z, v.w)));
    }
#pragma unroll
    for (int o = 16; o; o >>= 1)
        m = fmaxf(m, __shfl_xor_sync(0xFFFFFFFFu, m, o));
    if ((threadIdx.x & 31) == 0) smax[threadIdx.x >> 5] = m;
    __syncthreads();
    if (threadIdx.x < 32) {
        m = smax[threadIdx.x];
#pragma unroll
        for (int o = 16; o; o >>= 1)
            m = fmaxf(m, __shfl_xor_sync(0xFFFFFFFFu, m, o));
        if (threadIdx.x == 0) smax[0] = fmaxf(m, EPSF);
    }
    __syncthreads();
    float inv = __fdividef(1.f, smax[0]);
#pragma unroll
    for (int i = threadIdx.x; i < NPIX/4; i += 1024) {
        float4 v = o4[i];
        v.x *= inv; v.y *= inv; v.z *= inv; v.w *= inv;
        o4[i] = v;
    }
}

extern "C" void kernel_launch(void* const* d_in, const int* in_sizes, int n_in,
                              void* d_out, int out_size)
{
    const float* means      = (const float*)d_in[0];
    const float* raw_scales = (const float*)d_in[1];
    const float* rotors     = (const float*)d_in[2];
    const float* t_ptr      = (const float*)d_in[3];
    const float* angle_ptr  = (const float*)d_in[4];
    float* out = (float*)d_out;

    prep_kernel<<<NG/32, 32>>>(means, raw_scales, rotors, t_ptr, angle_ptr, out);
    render_kernel<<<dim3(NPIX/1024, NCHUNK), 256>>>(out);
    normalize_kernel<<<1, 1024>>>(out);
}